// round 6
// baseline (speedup 1.0000x reference)
#include <cuda_runtime.h>
#include <cuda_bf16.h>
#include <cstdint>

// B=8, N=2048, FEAT=16, pos = feats [0,2), radius = 0.25.
// Output [B, N, N] fp32 mask = 128 MiB compulsory stores.
// Single fused kernel: position reads come straight from nodes (1MB footprint,
// L2-resident), stores use streaming hint to ease L2 dirty-line pressure.
static constexpr int N_     = 2048;
static constexpr int BATCH_ = 8;
static constexpr int R_ROWS = 16;          // rows per block (register-reuse tile)
static constexpr float R2   = 0.0625f;     // 0.25^2

__device__ __forceinline__ int read_idx_arr(const int* __restrict__ a32, int b)
{
    // Handles both int32 and int64(small values) materialization of T/taus.
    const bool is64 = (a32[1] == 0) && (a32[0] != 0);
    return is64 ? a32[2 * b] : a32[b];
}

__global__ void __launch_bounds__(512, 3)
radius_edge_kernel(const float* __restrict__ nodes,
                   const int* __restrict__ T_arr,
                   const int* __restrict__ tau_arr,
                   float4* __restrict__ out)
{
    // grid = B * (N / R_ROWS) = 1024 blocks x 512 threads
    const int b  = blockIdx.x >> 7;            // /128
    const int i0 = (blockIdx.x & 127) * R_ROWS;
    const int t  = threadIdx.x;                // one float4 column-group each

    const int Tlo = read_idx_arr(T_arr, b);
    const int Thi = Tlo + read_idx_arr(tau_arr, b);  // active cols [Tlo, Thi)

    const int j0 = 4 * t;
    const float* __restrict__ nb = nodes + (size_t)b * N_ * 16;

    // Read this thread's 4 column positions ONCE (stride-64B float2 loads,
    // 1MB total footprint -> L2-resident), reuse across all 16 rows.
    float px[4], py[4];
    #pragma unroll
    for (int k = 0; k < 4; k++) {
        const float2 p = *(const float2*)(nb + (size_t)(j0 + k) * 16);
        px[k] = p.x;
        py[k] = p.y;
    }

    // Loop-invariant column-window mask.
    bool w[4];
    #pragma unroll
    for (int k = 0; k < 4; k++)
        w[k] = (j0 + k >= Tlo) && (j0 + k < Thi);

    float4* orow = out + ((size_t)b * N_ + i0) * (N_ / 4) + t;

    #pragma unroll 4
    for (int r = 0; r < R_ROWS; r++) {
        const int i = i0 + r;
        const float2 pi = *(const float2*)(nb + (size_t)i * 16); // uniform bcast, L1 hit

        float4 v;
        #pragma unroll
        for (int k = 0; k < 4; k++) {
            const float dx = pi.x - px[k];
            const float dy = pi.y - py[k];
            const bool  c  = w[k] & (i < j0 + k) & (fmaf(dx, dx, dy * dy) < R2);
            (&v.x)[k] = c ? 1.0f : 0.0f;
        }
        __stcs(&orow[(size_t)r * (N_ / 4)], v);  // streaming store, evict-first
    }
}

extern "C" void kernel_launch(void* const* d_in, const int* in_sizes, int n_in,
                              void* d_out, int out_size)
{
    const float* nodes   = (const float*)d_in[0];
    const int*   T_arr   = (const int*)d_in[1];
    const int*   tau_arr = (const int*)d_in[2];
    // d_in[3] = B scalar, unused (compile-time constants)

    const int blocks = BATCH_ * (N_ / R_ROWS);   // 1024
    radius_edge_kernel<<<blocks, 512>>>(nodes, T_arr, tau_arr, (float4*)d_out);
}